// round 3
// baseline (speedup 1.0000x reference)
#include <cuda_runtime.h>
#include <cuda_bf16.h>
#include <math.h>

// Problem constants
#define BB 8
#define SS 1536
#define DD 1024
#define S2 3072            // 2*SS
// exp(sim/T) = exp2(dot * (1/T)*log2(e)),  T = 0.05
#define KEXP 28.853900817779268f

// ---------------- device scratch (no allocations allowed) ----------------
__device__ float g_feats[(size_t)BB * S2 * DD];   // compacted normalized features, fp32
__device__ float g_posexp[BB * SS];               // exp(pos_sim) per compact token
__device__ int   g_cnt[BB];                       // active tokens per batch
__device__ int   g_slot[BB * SS];                 // compact slot per original token
__device__ float g_Ng[2][BB * S2];                // partial neg sums (2 deterministic halves)
__device__ int   g_mstride;                       // 1 if mask is uint8, 4 if int32 (LSB byte)

// ---------------- helpers ----------------
__device__ __forceinline__ float blockReduceF(float v) {
    __shared__ float sh[8];
    int lane = threadIdx.x & 31, w = threadIdx.x >> 5;
    #pragma unroll
    for (int m = 16; m; m >>= 1) v += __shfl_xor_sync(0xffffffffu, v, m);
    if (lane == 0) sh[w] = v;
    __syncthreads();
    if (w == 0) {
        float x = (lane < 8) ? sh[lane] : 0.0f;
        #pragma unroll
        for (int m = 4; m; m >>= 1) x += __shfl_xor_sync(0xffffffffu, x, m);
        if (lane == 0) sh[0] = x;
    }
    __syncthreads();
    float r = sh[0];
    __syncthreads();
    return r;
}

// ---------------- kernel 0: detect mask dtype (uint8 vs int32) ----------------
// If the bool mask was widened to int32, bytes 0..BB*SS-1 cover only the first
// BB*SS/4 elements (LSB-every-4-bytes, little endian) -> nonzero density ~0.125.
// If it stayed 1-byte, density ~0.5. Threshold at 0.3.
__global__ void kDet(const unsigned char* __restrict__ m) {
    __shared__ int s_tot;
    if (threadIdx.x == 0) s_tot = 0;
    __syncthreads();
    int c = 0;
    for (int i = threadIdx.x; i < BB * SS; i += 256) c += m[i] ? 1 : 0;
    #pragma unroll
    for (int w = 16; w; w >>= 1) c += __shfl_xor_sync(0xffffffffu, c, w);
    if ((threadIdx.x & 31) == 0) atomicAdd(&s_tot, c);
    __syncthreads();
    if (threadIdx.x == 0)
        g_mstride = (s_tot > (BB * SS * 3) / 10) ? 1 : 4;
}

// ---------------- kernel A: per-batch prefix scan + pad zeroing ----------------
__global__ void kA_scan(const unsigned char* __restrict__ mask) {
    int b = blockIdx.x;
    int tid = threadIdx.x;               // 256 threads
    const int CH = SS / 256;             // 6
    int stride = g_mstride;
    __shared__ int cnts[256];
    __shared__ int s_total;

    unsigned char mv[CH];
    int cnt = 0;
    int base = tid * CH;
    #pragma unroll
    for (int j = 0; j < CH; j++) {
        mv[j] = mask[((size_t)b * SS + base + j) * stride];
        cnt += mv[j] ? 1 : 0;
    }
    cnts[tid] = cnt;
    __syncthreads();
    // Hillis-Steele inclusive scan over 256 thread counts
    for (int off = 1; off < 256; off <<= 1) {
        int v = (tid >= off) ? cnts[tid - off] : 0;
        __syncthreads();
        cnts[tid] += v;
        __syncthreads();
    }
    int run = cnts[tid] - cnt;           // exclusive prefix
    #pragma unroll
    for (int j = 0; j < CH; j++) {
        if (mv[j]) g_slot[b * SS + base + j] = run++;
    }
    if (tid == 255) { g_cnt[b] = cnts[255]; s_total = cnts[255]; }
    __syncthreads();

    // zero pad rows [2*nb, round64(2*nb)) so Gram tiles never read garbage
    int n2 = 2 * s_total;
    int pad_end = ((n2 + 63) / 64) * 64;
    if (pad_end > S2) pad_end = S2;
    int nz = (pad_end - n2) * DD;
    float* dst = g_feats + ((size_t)b * S2 + n2) * DD;
    for (int i = tid; i < nz; i += 256) dst[i] = 0.0f;
}

// ---------------- kernel B: normalize + compact + positive pair ----------------
__global__ void kB_norm(const float* __restrict__ h1, const float* __restrict__ h2,
                        const unsigned char* __restrict__ mask) {
    int g = blockIdx.x;
    int b = g / SS, i = g % SS;
    if (!mask[((size_t)b * SS + i) * g_mstride]) return;   // whole block uniform
    int tid = threadIdx.x;                     // 256 threads, 4 floats each
    int c  = g_slot[b * SS + i];
    int nb = g_cnt[b];

    const float4* p1 = (const float4*)(h1 + ((size_t)b * SS + i) * DD);
    const float4* p2 = (const float4*)(h2 + ((size_t)b * SS + i) * DD);
    float4 v1 = p1[tid];
    float4 v2 = p2[tid];

    float ss1 = blockReduceF(v1.x * v1.x + v1.y * v1.y + v1.z * v1.z + v1.w * v1.w);
    float ss2 = blockReduceF(v2.x * v2.x + v2.y * v2.y + v2.z * v2.z + v2.w * v2.w);
    float inv1 = 1.0f / fmaxf(sqrtf(ss1), 1e-12f);
    float inv2 = 1.0f / fmaxf(sqrtf(ss2), 1e-12f);

    float4 f1 = make_float4(v1.x * inv1, v1.y * inv1, v1.z * inv1, v1.w * inv1);
    float4 f2 = make_float4(v2.x * inv2, v2.y * inv2, v2.z * inv2, v2.w * inv2);

    ((float4*)(g_feats + ((size_t)b * S2 + c) * DD))[tid] = f1;
    ((float4*)(g_feats + ((size_t)b * S2 + nb + c) * DD))[tid] = f2;

    float d = blockReduceF(f1.x * f2.x + f1.y * f2.y + f1.z * f2.z + f1.w * f2.w);
    if (tid == 0) g_posexp[b * SS + c] = exp2f(d * KEXP);
}

// ---------------- kernel C: fused Gram + exp + mask + row-sum ----------------
// 64x64 block tile, 256 threads (16x16), 4x4 micro-tile.
// grid = (48 rowblocks, B, 2 col-halves); deterministic (no atomics).
__global__ void __launch_bounds__(256, 2) kC_gram() {
    int b = blockIdx.y;
    int z = blockIdx.z;
    int nb = g_cnt[b];
    int n2 = 2 * nb;
    int r0 = blockIdx.x * 64;
    if (r0 >= n2) return;

    const float* F = g_feats + (size_t)b * S2 * DD;
    __shared__ float As[16][68];
    __shared__ float Bs[16][68];

    int tid = threadIdx.x;
    int ty = tid >> 4, tx = tid & 15;
    int lr = tid >> 2, kq = tid & 3;      // loader mapping: row-in-tile, quad

    float rsum[4] = {0.f, 0.f, 0.f, 0.f};
    int nct = (n2 + 63) >> 6;

    for (int ct = z; ct < nct; ct += 2) {
        int c0 = ct << 6;
        float acc[4][4];
        #pragma unroll
        for (int aa = 0; aa < 4; aa++)
            #pragma unroll
            for (int qq = 0; qq < 4; qq++) acc[aa][qq] = 0.0f;

        for (int kt = 0; kt < DD; kt += 16) {
            float4 av = *(const float4*)(F + (size_t)(r0 + lr) * DD + kt + kq * 4);
            float4 bv = *(const float4*)(F + (size_t)(c0 + lr) * DD + kt + kq * 4);
            __syncthreads();   // previous compute done before overwrite
            As[kq * 4 + 0][lr] = av.x; As[kq * 4 + 1][lr] = av.y;
            As[kq * 4 + 2][lr] = av.z; As[kq * 4 + 3][lr] = av.w;
            Bs[kq * 4 + 0][lr] = bv.x; Bs[kq * 4 + 1][lr] = bv.y;
            Bs[kq * 4 + 2][lr] = bv.z; Bs[kq * 4 + 3][lr] = bv.w;
            __syncthreads();
            #pragma unroll
            for (int k = 0; k < 16; k++) {
                float4 a  = *(const float4*)&As[k][ty * 4];   // broadcast across tx
                float4 bq = *(const float4*)&Bs[k][tx * 4];
                acc[0][0] += a.x * bq.x; acc[0][1] += a.x * bq.y; acc[0][2] += a.x * bq.z; acc[0][3] += a.x * bq.w;
                acc[1][0] += a.y * bq.x; acc[1][1] += a.y * bq.y; acc[1][2] += a.y * bq.z; acc[1][3] += a.y * bq.w;
                acc[2][0] += a.z * bq.x; acc[2][1] += a.z * bq.y; acc[2][2] += a.z * bq.z; acc[2][3] += a.z * bq.w;
                acc[3][0] += a.w * bq.x; acc[3][1] += a.w * bq.y; acc[3][2] += a.w * bq.z; acc[3][3] += a.w * bq.w;
            }
        }
        // epilogue: exp + negative-pair mask + row accumulate
        #pragma unroll
        for (int aa = 0; aa < 4; aa++) {
            int row = r0 + ty * 4 + aa;
            if (row >= n2) continue;
            int rm = (row < nb) ? row : row - nb;
            float s = 0.0f;
            #pragma unroll
            for (int qq = 0; qq < 4; qq++) {
                int col = c0 + tx * 4 + qq;
                if (col < n2) {
                    int cm = (col < nb) ? col : col - nb;
                    if (cm != rm) s += exp2f(acc[aa][qq] * KEXP);
                }
            }
            rsum[aa] += s;
        }
    }

    // reduce row sums across the 16 tx lanes; tx==0 writes (deterministic)
    #pragma unroll
    for (int aa = 0; aa < 4; aa++) {
        float v = rsum[aa];
        #pragma unroll
        for (int m = 8; m; m >>= 1) v += __shfl_xor_sync(0xffffffffu, v, m);
        if (tx == 0) {
            int row = r0 + ty * 4 + aa;
            if (row < n2) g_Ng[z][b * S2 + row] = v;
        }
    }
}

// ---------------- kernel D: final loss reduction ----------------
__global__ void kD_final(float* __restrict__ out) {
    __shared__ double sh[8];
    int tid = threadIdx.x;    // 256
    int lane = tid & 31, w = tid >> 5;
    double tot = 0.0;
    for (int b = 0; b < BB; b++) {
        int nb = g_cnt[b];
        int n2 = 2 * nb;
        double local = 0.0;
        for (int idx = tid; idx < n2; idx += 256) {
            int c = (idx < nb) ? idx : idx - nb;
            float pos = g_posexp[b * SS + c];
            float Ng  = g_Ng[0][b * S2 + idx] + g_Ng[1][b * S2 + idx];
            // -log(pos/(Ng+pos)) = log1p(Ng/pos)
            local += (double)log1pf(Ng / pos);
        }
        #pragma unroll
        for (int m = 16; m; m >>= 1) local += __shfl_xor_sync(0xffffffffu, local, m);
        if (lane == 0) sh[w] = local;
        __syncthreads();
        if (w == 0) {
            double x = (lane < 8) ? sh[lane] : 0.0;
            #pragma unroll
            for (int m = 4; m; m >>= 1) x += __shfl_xor_sync(0xffffffffu, x, m);
            if (lane == 0 && n2 > 0) tot += x / (double)n2;
        }
        __syncthreads();
    }
    if (tid == 0) out[0] = (float)(tot / (double)BB);
}

// ---------------- launch ----------------
extern "C" void kernel_launch(void* const* d_in, const int* in_sizes, int n_in,
                              void* d_out, int out_size) {
    const float* h1 = (const float*)d_in[0];
    const float* h2 = (const float*)d_in[1];
    const unsigned char* mask = (const unsigned char*)d_in[2];
    float* out = (float*)d_out;

    kDet<<<1, 256>>>(mask);
    kA_scan<<<BB, 256>>>(mask);
    kB_norm<<<BB * SS, 256>>>(h1, h2, mask);
    dim3 gc(S2 / 64, BB, 2);
    kC_gram<<<gc, 256>>>();
    kD_final<<<1, 256>>>(out);
}

// round 5
// speedup vs baseline: 5.7219x; 5.7219x over previous
#include <cuda_runtime.h>
#include <cuda_bf16.h>
#include <math.h>
#include <stdint.h>

// Problem constants
#define BB 8
#define SS 1536
#define DD 1024
#define S2 3072            // 2*SS
// exp(sim/T) = exp2(dot * (1/T)*log2(e)),  T = 0.05
#define KEXP 28.853900817779268f

// ---------------- device scratch ----------------
__device__ __align__(16) __nv_bfloat16 g_fb[(size_t)BB * S2 * DD]; // compact bf16 feats
__device__ float g_posexp[BB * SS];
__device__ int   g_cnt[BB];
__device__ int   g_slot[BB * SS];
__device__ float g_Ng[2][BB * S2];
__device__ int   g_mstride;   // 1 = uint8 mask, 4 = int32 mask (LSB byte)

// ---------------- PTX helpers (all base-sm_80+ instructions) ----------------
__device__ __forceinline__ uint32_t smem_u32(const void* p) {
    uint32_t a;
    asm("{ .reg .u64 t; cvta.to.shared.u64 t, %1; cvt.u32.u64 %0, t; }" : "=r"(a) : "l"(p));
    return a;
}
#define SWZ128(o) ((o) ^ (((o) >> 3) & 0x70))

#define CP16(dst, src) \
    asm volatile("cp.async.cg.shared.global [%0], [%1], 16;" :: "r"(dst), "l"(src) : "memory")
#define CP_COMMIT() asm volatile("cp.async.commit_group;" ::: "memory")
#define CP_WAIT1()  asm volatile("cp.async.wait_group 1;" ::: "memory")
#define CP_WAIT0()  asm volatile("cp.async.wait_group 0;" ::: "memory")

#define LDSM_X4(r, addr) \
    asm volatile("ldmatrix.sync.aligned.m8n8.x4.shared.b16 {%0,%1,%2,%3}, [%4];" \
        : "=r"((r)[0]), "=r"((r)[1]), "=r"((r)[2]), "=r"((r)[3]) : "r"(addr))

#define MMA16816(d, a, b0v, b1v) \
    asm volatile("mma.sync.aligned.m16n8k16.row.col.f32.bf16.bf16.f32 " \
        "{%0,%1,%2,%3}, {%4,%5,%6,%7}, {%8,%9}, {%0,%1,%2,%3};" \
        : "+f"((d)[0]), "+f"((d)[1]), "+f"((d)[2]), "+f"((d)[3]) \
        : "r"((a)[0]), "r"((a)[1]), "r"((a)[2]), "r"((a)[3]), "r"(b0v), "r"(b1v))

// ---------------- generic helpers ----------------
__device__ __forceinline__ float blockReduceF(float v) {
    __shared__ float sh[8];
    int lane = threadIdx.x & 31, w = threadIdx.x >> 5;
    #pragma unroll
    for (int m = 16; m; m >>= 1) v += __shfl_xor_sync(0xffffffffu, v, m);
    if (lane == 0) sh[w] = v;
    __syncthreads();
    if (w == 0) {
        float x = (lane < 8) ? sh[lane] : 0.0f;
        #pragma unroll
        for (int m = 4; m; m >>= 1) x += __shfl_xor_sync(0xffffffffu, x, m);
        if (lane == 0) sh[0] = x;
    }
    __syncthreads();
    float r = sh[0];
    __syncthreads();
    return r;
}

// ---------------- kernel 0: detect mask dtype ----------------
__global__ void kDet(const unsigned char* __restrict__ m) {
    __shared__ int s_tot;
    if (threadIdx.x == 0) s_tot = 0;
    __syncthreads();
    int c = 0;
    for (int i = threadIdx.x; i < BB * SS; i += 256) c += m[i] ? 1 : 0;
    #pragma unroll
    for (int w = 16; w; w >>= 1) c += __shfl_xor_sync(0xffffffffu, c, w);
    if ((threadIdx.x & 31) == 0) atomicAdd(&s_tot, c);
    __syncthreads();
    if (threadIdx.x == 0)
        g_mstride = (s_tot > (BB * SS * 3) / 10) ? 1 : 4;
}

// ---------------- kernel A: prefix scan + pad zeroing (to 128 rows) ----------------
__global__ void kA_scan(const unsigned char* __restrict__ mask) {
    int b = blockIdx.x;
    int tid = threadIdx.x;               // 256 threads
    const int CH = SS / 256;             // 6
    int stride = g_mstride;
    __shared__ int cnts[256];
    __shared__ int s_total;

    unsigned char mv[CH];
    int cnt = 0;
    int base = tid * CH;
    #pragma unroll
    for (int j = 0; j < CH; j++) {
        mv[j] = mask[((size_t)b * SS + base + j) * stride];
        cnt += mv[j] ? 1 : 0;
    }
    cnts[tid] = cnt;
    __syncthreads();
    for (int off = 1; off < 256; off <<= 1) {
        int v = (tid >= off) ? cnts[tid - off] : 0;
        __syncthreads();
        cnts[tid] += v;
        __syncthreads();
    }
    int run = cnts[tid] - cnt;
    #pragma unroll
    for (int j = 0; j < CH; j++) {
        if (mv[j]) g_slot[b * SS + base + j] = run++;
    }
    if (tid == 255) { g_cnt[b] = cnts[255]; s_total = cnts[255]; }
    __syncthreads();

    // zero bf16 pad rows [2*nb, round128(2*nb))
    int n2 = 2 * s_total;
    int pad_end = ((n2 + 127) / 128) * 128;
    if (pad_end > S2) pad_end = S2;
    int nz = (pad_end - n2) * DD / 2;   // uint32 count
    uint32_t* dst = (uint32_t*)(g_fb + ((size_t)b * S2 + n2) * DD);
    for (int i = tid; i < nz; i += 256) dst[i] = 0u;
}

// ---------------- kernel B: normalize + compact(bf16) + positive pair(fp32) ----------------
__global__ void kB_norm(const float* __restrict__ h1, const float* __restrict__ h2,
                        const unsigned char* __restrict__ mask) {
    int g = blockIdx.x;
    int b = g / SS, i = g % SS;
    if (!mask[((size_t)b * SS + i) * g_mstride]) return;
    int tid = threadIdx.x;                     // 256 threads, 4 floats each
    int c  = g_slot[b * SS + i];
    int nb = g_cnt[b];

    const float4* p1 = (const float4*)(h1 + ((size_t)b * SS + i) * DD);
    const float4* p2 = (const float4*)(h2 + ((size_t)b * SS + i) * DD);
    float4 v1 = p1[tid];
    float4 v2 = p2[tid];

    float ss1 = blockReduceF(v1.x * v1.x + v1.y * v1.y + v1.z * v1.z + v1.w * v1.w);
    float ss2 = blockReduceF(v2.x * v2.x + v2.y * v2.y + v2.z * v2.z + v2.w * v2.w);
    float inv1 = 1.0f / fmaxf(sqrtf(ss1), 1e-12f);
    float inv2 = 1.0f / fmaxf(sqrtf(ss2), 1e-12f);

    float4 f1 = make_float4(v1.x * inv1, v1.y * inv1, v1.z * inv1, v1.w * inv1);
    float4 f2 = make_float4(v2.x * inv2, v2.y * inv2, v2.z * inv2, v2.w * inv2);

    __nv_bfloat162 a0 = __floats2bfloat162_rn(f1.x, f1.y);
    __nv_bfloat162 a1 = __floats2bfloat162_rn(f1.z, f1.w);
    __nv_bfloat162 b0 = __floats2bfloat162_rn(f2.x, f2.y);
    __nv_bfloat162 b1 = __floats2bfloat162_rn(f2.z, f2.w);
    uint2 pa = make_uint2(*(uint32_t*)&a0, *(uint32_t*)&a1);
    uint2 pb = make_uint2(*(uint32_t*)&b0, *(uint32_t*)&b1);
    ((uint2*)(g_fb + ((size_t)b * S2 + c) * DD))[tid] = pa;
    ((uint2*)(g_fb + ((size_t)b * S2 + nb + c) * DD))[tid] = pb;

    // positive-pair dot in fp32 (full precision)
    float d = blockReduceF(f1.x * f2.x + f1.y * f2.y + f1.z * f2.z + f1.w * f2.w);
    if (tid == 0) g_posexp[b * SS + c] = exp2f(d * KEXP);
}

// ---------------- kernel C: HMMA Gram + fused exp/mask/rowsum ----------------
// 256 threads (8 warps), CTA tile 128x128, warp tile 32x64 (2x8 m16n8k16).
// K in 64-elem bf16 chunks (128B SW128 rows), double-buffered cp.async.
// grid = (24 rowblocks, B, 2 col halves). Deterministic, no atomics.
#define AOF0 0u
#define BOF0 16384u
#define AOF1 32768u
#define BOF1 49152u
#define SMC_TOTAL 65536

__device__ __forceinline__ void load_chunk(uint32_t sbase, uint32_t aof, uint32_t bof,
                                           const __nv_bfloat16* F, int r0, int c0,
                                           int kc, int tid) {
    #pragma unroll
    for (int i = 0; i < 4; i++) {
        int v = tid + i * 256;
        int r = v >> 3, c = v & 7;
        const char* srcA = (const char*)F + (((size_t)(r0 + r)) * DD + kc * 64 + c * 8) * 2;
        CP16(sbase + aof + SWZ128(r * 128 + c * 16), srcA);
        const char* srcB = (const char*)F + (((size_t)(c0 + r)) * DD + kc * 64 + c * 8) * 2;
        CP16(sbase + bof + SWZ128(r * 128 + c * 16), srcB);
    }
}

__global__ void __launch_bounds__(256, 1) kC_gram() {
    extern __shared__ char smem[];
    int b = blockIdx.y;
    int z = blockIdx.z;
    int nb = g_cnt[b];
    int n2 = 2 * nb;
    int r0 = blockIdx.x * 128;
    if (r0 >= n2) return;

    uint32_t sbase = smem_u32(smem);
    const __nv_bfloat16* F = g_fb + (size_t)b * S2 * DD;
    int tid = threadIdx.x;
    int wid = tid >> 5, l = tid & 31;
    int wm = wid & 3, wn = wid >> 2;
    int g4 = l >> 2, t4 = l & 3;
    int nct = (n2 + 127) >> 7;

    const uint32_t AOF[2] = {AOF0, AOF1};
    const uint32_t BOF[2] = {BOF0, BOF1};

    // per-thread output rows: mi in {0,1}, di in {0,1}
    int rmv[4];
    #pragma unroll
    for (int mi = 0; mi < 2; mi++)
        #pragma unroll
        for (int di = 0; di < 2; di++) {
            int row = r0 + wm * 32 + mi * 16 + di * 8 + g4;
            rmv[mi * 2 + di] = (row < nb) ? row : row - nb;
        }
    float rsum[4] = {0.f, 0.f, 0.f, 0.f};

    for (int ct = z; ct < nct; ct += 2) {
        int c0 = ct << 7;
        float acc[2][8][4];
        #pragma unroll
        for (int mi = 0; mi < 2; mi++)
            #pragma unroll
            for (int ni = 0; ni < 8; ni++)
                #pragma unroll
                for (int j = 0; j < 4; j++) acc[mi][ni][j] = 0.0f;

        load_chunk(sbase, AOF[0], BOF[0], F, r0, c0, 0, tid);
        CP_COMMIT();

        for (int kc = 0; kc < 16; kc++) {
            int buf = kc & 1;
            if (kc < 15) {
                load_chunk(sbase, AOF[buf ^ 1], BOF[buf ^ 1], F, r0, c0, kc + 1, tid);
                CP_COMMIT();
                CP_WAIT1();
            } else {
                CP_WAIT0();
            }
            __syncthreads();

            uint32_t abase = sbase + AOF[buf];
            uint32_t bbase = sbase + BOF[buf];
            #pragma unroll
            for (int s = 0; s < 4; s++) {
                uint32_t afr[2][4], bfr[4][4];
                #pragma unroll
                for (int mi = 0; mi < 2; mi++) {
                    uint32_t off = SWZ128((uint32_t)((wm * 32 + mi * 16 + (l & 15)) * 128
                                                     + s * 32 + (l >> 4) * 16));
                    LDSM_X4(afr[mi], abase + off);
                }
                #pragma unroll
                for (int p = 0; p < 4; p++) {
                    uint32_t off = SWZ128((uint32_t)((wn * 64 + p * 16 + ((l >> 4) & 1) * 8
                                                     + (l & 7)) * 128
                                                     + s * 32 + ((l >> 3) & 1) * 16));
                    LDSM_X4(bfr[p], bbase + off);
                }
                #pragma unroll
                for (int mi = 0; mi < 2; mi++)
                    #pragma unroll
                    for (int ni = 0; ni < 8; ni++)
                        MMA16816(acc[mi][ni], afr[mi], bfr[ni >> 1][(ni & 1) * 2],
                                 bfr[ni >> 1][(ni & 1) * 2 + 1]);
            }
            __syncthreads();
        }

        // epilogue: exp + neg-pair mask + row accumulate (registers only)
        #pragma unroll
        for (int mi = 0; mi < 2; mi++)
            #pragma unroll
            for (int ni = 0; ni < 8; ni++)
                #pragma unroll
                for (int j = 0; j < 4; j++) {
                    int col = c0 + wn * 64 + ni * 8 + t4 * 2 + (j & 1);
                    int cm = (col < nb) ? col : col - nb;
                    int ri = mi * 2 + (j >> 1);
                    if (col < n2 && cm != rmv[ri])
                        rsum[ri] += exp2f(acc[mi][ni][j] * KEXP);
                }
    }

    // reduce across the 4 lanes of each group (cols), then across the 2 n-warps
    #pragma unroll
    for (int j = 0; j < 4; j++) {
        rsum[j] += __shfl_xor_sync(0xffffffffu, rsum[j], 1);
        rsum[j] += __shfl_xor_sync(0xffffffffu, rsum[j], 2);
    }
    float* red = (float*)smem;  // reuse (all async loads drained, compute synced)
    __syncthreads();
    if (t4 == 0) {
        #pragma unroll
        for (int mi = 0; mi < 2; mi++)
            #pragma unroll
            for (int di = 0; di < 2; di++) {
                int rl = wm * 32 + mi * 16 + di * 8 + g4;
                red[rl * 2 + wn] = rsum[mi * 2 + di];
            }
    }
    __syncthreads();
    if (tid < 128) {
        int row = r0 + tid;
        if (row < n2)
            g_Ng[z][b * S2 + row] = red[tid * 2 + 0] + red[tid * 2 + 1];
    }
}

// ---------------- kernel D: final loss reduction ----------------
__global__ void kD_final(float* __restrict__ out) {
    __shared__ double sh[8];
    int tid = threadIdx.x;    // 256
    int lane = tid & 31, w = tid >> 5;
    double tot = 0.0;
    for (int b = 0; b < BB; b++) {
        int nb = g_cnt[b];
        int n2 = 2 * nb;
        double local = 0.0;
        for (int idx = tid; idx < n2; idx += 256) {
            int c = (idx < nb) ? idx : idx - nb;
            float pos = g_posexp[b * SS + c];
            float Ng  = g_Ng[0][b * S2 + idx] + g_Ng[1][b * S2 + idx];
            local += (double)log1pf(Ng / pos);
        }
        #pragma unroll
        for (int m = 16; m; m >>= 1) local += __shfl_xor_sync(0xffffffffu, local, m);
        if (lane == 0) sh[w] = local;
        __syncthreads();
        if (w == 0) {
            double x = (lane < 8) ? sh[lane] : 0.0;
            #pragma unroll
            for (int m = 4; m; m >>= 1) x += __shfl_xor_sync(0xffffffffu, x, m);
            if (lane == 0 && n2 > 0) tot += x / (double)n2;
        }
        __syncthreads();
    }
    if (tid == 0) out[0] = (float)(tot / (double)BB);
}

// ---------------- launch ----------------
extern "C" void kernel_launch(void* const* d_in, const int* in_sizes, int n_in,
                              void* d_out, int out_size) {
    const float* h1 = (const float*)d_in[0];
    const float* h2 = (const float*)d_in[1];
    const unsigned char* mask = (const unsigned char*)d_in[2];
    float* out = (float*)d_out;

    static int s_attr_done = 0;
    if (!s_attr_done) {
        cudaFuncSetAttribute(kC_gram, cudaFuncAttributeMaxDynamicSharedMemorySize, SMC_TOTAL);
        s_attr_done = 1;
    }

    kDet<<<1, 256>>>(mask);
    kA_scan<<<BB, 256>>>(mask);
    kB_norm<<<BB * SS, 256>>>(h1, h2, mask);
    dim3 gc(S2 / 128, BB, 2);
    kC_gram<<<gc, 256, SMC_TOTAL>>>();
    kD_final<<<1, 256>>>(out);
}

// round 7
// speedup vs baseline: 6.0538x; 1.0580x over previous
#include <cuda_runtime.h>
#include <cuda_bf16.h>
#include <math.h>
#include <stdint.h>

// Problem constants
#define BB 8
#define SS 1536
#define DD 1024
#define S2 3072            // 2*SS
// exp(sim/T) = exp2(dot * (1/T)*log2(e)),  T = 0.05
#define KEXP 28.853900817779268f

// ---------------- device scratch ----------------
__device__ __align__(16) __nv_bfloat16 g_fb[(size_t)BB * S2 * DD]; // compact bf16 feats
__device__ float g_posexp[BB * SS];
__device__ int   g_cnt[BB];
__device__ int   g_slot[BB * SS];
__device__ float g_Ng[2][BB * S2];
__device__ int   g_mstride;   // 1 = uint8 mask, 4 = int32 mask (LSB byte)

// ---------------- PTX helpers (base sm_80+ instructions only) ----------------
__device__ __forceinline__ uint32_t smem_u32(const void* p) {
    uint32_t a;
    asm("{ .reg .u64 t; cvta.to.shared.u64 t, %1; cvt.u32.u64 %0, t; }" : "=r"(a) : "l"(p));
    return a;
}
#define SWZ128(o) ((o) ^ (((o) >> 3) & 0x70))

#define CP16(dst, src) \
    asm volatile("cp.async.cg.shared.global [%0], [%1], 16;" :: "r"(dst), "l"(src) : "memory")
#define CP_COMMIT() asm volatile("cp.async.commit_group;" ::: "memory")
#define CP_WAIT1()  asm volatile("cp.async.wait_group 1;" ::: "memory")

#define LDSM_X4(r, addr) \
    asm volatile("ldmatrix.sync.aligned.m8n8.x4.shared.b16 {%0,%1,%2,%3}, [%4];" \
        : "=r"((r)[0]), "=r"((r)[1]), "=r"((r)[2]), "=r"((r)[3]) : "r"(addr))

#define MMA16816(d, a, b0v, b1v) \
    asm volatile("mma.sync.aligned.m16n8k16.row.col.f32.bf16.bf16.f32 " \
        "{%0,%1,%2,%3}, {%4,%5,%6,%7}, {%8,%9}, {%0,%1,%2,%3};" \
        : "+f"((d)[0]), "+f"((d)[1]), "+f"((d)[2]), "+f"((d)[3]) \
        : "r"((a)[0]), "r"((a)[1]), "r"((a)[2]), "r"((a)[3]), "r"(b0v), "r"(b1v))

// ---------------- generic helpers ----------------
__device__ __forceinline__ float blockReduceF(float v) {
    __shared__ float sh[8];
    int lane = threadIdx.x & 31, w = threadIdx.x >> 5;
    #pragma unroll
    for (int m = 16; m; m >>= 1) v += __shfl_xor_sync(0xffffffffu, v, m);
    if (lane == 0) sh[w] = v;
    __syncthreads();
    if (w == 0) {
        float x = (lane < 8) ? sh[lane] : 0.0f;
        #pragma unroll
        for (int m = 4; m; m >>= 1) x += __shfl_xor_sync(0xffffffffu, x, m);
        if (lane == 0) sh[0] = x;
    }
    __syncthreads();
    float r = sh[0];
    __syncthreads();
    return r;
}

// ---------------- kernel A: detect mask dtype + prefix scan + pad zeroing ----------------
__global__ void kA_scan(const unsigned char* __restrict__ mask) {
    int b = blockIdx.x;
    int tid = threadIdx.x;               // 256 threads
    const int CH = SS / 256;             // 6
    __shared__ int cnts[256];
    __shared__ int s_total;
    __shared__ int s_stride;

    // --- mask dtype detection (every block redundantly; same result) ---
    {
        int c = 0;
        for (int i = tid; i < BB * SS; i += 256) c += mask[i] ? 1 : 0;
        #pragma unroll
        for (int m = 16; m; m >>= 1) c += __shfl_xor_sync(0xffffffffu, c, m);
        if ((tid & 31) == 0) cnts[tid >> 5] = c;
        __syncthreads();
        if (tid == 0) {
            int t = 0;
            #pragma unroll
            for (int i = 0; i < 8; i++) t += cnts[i];
            int st = (t > (BB * SS * 3) / 10) ? 1 : 4;
            s_stride = st;
            g_mstride = st;              // for kB (all blocks write same value)
        }
        __syncthreads();
    }
    int stride = s_stride;
    __syncthreads();

    unsigned char mv[CH];
    int cnt = 0;
    int base = tid * CH;
    #pragma unroll
    for (int j = 0; j < CH; j++) {
        mv[j] = mask[((size_t)b * SS + base + j) * stride];
        cnt += mv[j] ? 1 : 0;
    }
    cnts[tid] = cnt;
    __syncthreads();
    for (int off = 1; off < 256; off <<= 1) {
        int v = (tid >= off) ? cnts[tid - off] : 0;
        __syncthreads();
        cnts[tid] += v;
        __syncthreads();
    }
    int run = cnts[tid] - cnt;
    #pragma unroll
    for (int j = 0; j < CH; j++) {
        if (mv[j]) g_slot[b * SS + base + j] = run++;
    }
    if (tid == 255) { g_cnt[b] = cnts[255]; s_total = cnts[255]; }
    __syncthreads();

    // zero bf16 pad rows [2*nb, round128(2*nb))
    int n2 = 2 * s_total;
    int pad_end = ((n2 + 127) / 128) * 128;
    if (pad_end > S2) pad_end = S2;
    int nz = (pad_end - n2) * DD / 2;   // uint32 count
    uint32_t* dst = (uint32_t*)(g_fb + ((size_t)b * S2 + n2) * DD);
    for (int i = tid; i < nz; i += 256) dst[i] = 0u;
}

// ---------------- kernel B: normalize + compact(bf16) + positive pair(fp32) ----------------
__global__ void kB_norm(const float* __restrict__ h1, const float* __restrict__ h2,
                        const unsigned char* __restrict__ mask) {
    int g = blockIdx.x;
    int b = g / SS, i = g % SS;
    if (!mask[((size_t)b * SS + i) * g_mstride]) return;
    int tid = threadIdx.x;                     // 256 threads, 4 floats each
    int c  = g_slot[b * SS + i];
    int nb = g_cnt[b];

    const float4* p1 = (const float4*)(h1 + ((size_t)b * SS + i) * DD);
    const float4* p2 = (const float4*)(h2 + ((size_t)b * SS + i) * DD);
    float4 v1 = p1[tid];
    float4 v2 = p2[tid];

    float ss1 = blockReduceF(v1.x * v1.x + v1.y * v1.y + v1.z * v1.z + v1.w * v1.w);
    float ss2 = blockReduceF(v2.x * v2.x + v2.y * v2.y + v2.z * v2.z + v2.w * v2.w);
    float inv1 = 1.0f / fmaxf(sqrtf(ss1), 1e-12f);
    float inv2 = 1.0f / fmaxf(sqrtf(ss2), 1e-12f);

    float4 f1 = make_float4(v1.x * inv1, v1.y * inv1, v1.z * inv1, v1.w * inv1);
    float4 f2 = make_float4(v2.x * inv2, v2.y * inv2, v2.z * inv2, v2.w * inv2);

    __nv_bfloat162 a0 = __floats2bfloat162_rn(f1.x, f1.y);
    __nv_bfloat162 a1 = __floats2bfloat162_rn(f1.z, f1.w);
    __nv_bfloat162 b0 = __floats2bfloat162_rn(f2.x, f2.y);
    __nv_bfloat162 b1 = __floats2bfloat162_rn(f2.z, f2.w);
    uint2 pa = make_uint2(*(uint32_t*)&a0, *(uint32_t*)&a1);
    uint2 pb = make_uint2(*(uint32_t*)&b0, *(uint32_t*)&b1);
    ((uint2*)(g_fb + ((size_t)b * S2 + c) * DD))[tid] = pa;
    ((uint2*)(g_fb + ((size_t)b * S2 + nb + c) * DD))[tid] = pb;

    // positive-pair dot in fp32 (full precision)
    float d = blockReduceF(f1.x * f2.x + f1.y * f2.y + f1.z * f2.z + f1.w * f2.w);
    if (tid == 0) g_posexp[b * SS + c] = exp2f(d * KEXP);
}

// ---------------- kernel C: HMMA Gram + fused exp/mask/rowsum ----------------
// 256 threads (8 warps), CTA tile 128x128, warp tile 32x64 (2x8 m16n8k16).
// 3-stage cp.async pipeline (K-chunk 64), ONE __syncthreads per k-chunk,
// register double-buffered ldmatrix fragments.
// grid = (24 rowblocks, B, 2 col halves). Deterministic, no atomics.
#define STG 32768u
#define SMC_TOTAL (3 * 32768)

__device__ __forceinline__ void load_stage(uint32_t sbase, int st, const __nv_bfloat16* F,
                                           int r0, int c0, int kc, int tid) {
    uint32_t aof = (uint32_t)st * STG;
    uint32_t bof = aof + 16384u;
    #pragma unroll
    for (int i = 0; i < 4; i++) {
        int v = tid + i * 256;
        int r = v >> 3, c = v & 7;
        const char* srcA = (const char*)F + (((size_t)(r0 + r)) * DD + kc * 64 + c * 8) * 2;
        CP16(sbase + aof + SWZ128(r * 128 + c * 16), srcA);
        const char* srcB = (const char*)F + (((size_t)(c0 + r)) * DD + kc * 64 + c * 8) * 2;
        CP16(sbase + bof + SWZ128(r * 128 + c * 16), srcB);
    }
}

__device__ __forceinline__ void ldsm_frag(uint32_t abase, uint32_t bbase, int s,
                                          int l, int wm, int wn,
                                          uint32_t afr[2][4], uint32_t bfr[4][4]) {
    #pragma unroll
    for (int mi = 0; mi < 2; mi++) {
        uint32_t off = SWZ128((uint32_t)((wm * 32 + mi * 16 + (l & 15)) * 128
                                         + s * 32 + (l >> 4) * 16));
        LDSM_X4(afr[mi], abase + off);
    }
    #pragma unroll
    for (int p = 0; p < 4; p++) {
        uint32_t off = SWZ128((uint32_t)((wn * 64 + p * 16 + ((l >> 4) & 1) * 8
                                         + (l & 7)) * 128
                                         + s * 32 + ((l >> 3) & 1) * 16));
        LDSM_X4(bfr[p], bbase + off);
    }
}

__global__ void __launch_bounds__(256, 1) kC_gram() {
    extern __shared__ char smem[];
    int b = blockIdx.y;
    int z = blockIdx.z;
    int nb = g_cnt[b];
    int n2 = 2 * nb;
    int r0 = blockIdx.x * 128;
    if (r0 >= n2) return;

    uint32_t sbase = smem_u32(smem);
    const __nv_bfloat16* F = g_fb + (size_t)b * S2 * DD;
    int tid = threadIdx.x;
    int wid = tid >> 5, l = tid & 31;
    int wm = wid & 3, wn = wid >> 2;
    int g4 = l >> 2, t4 = l & 3;
    int nct = (n2 + 127) >> 7;

    // per-thread output rows: mi in {0,1}, di in {0,1}
    int rmv[4];
    #pragma unroll
    for (int mi = 0; mi < 2; mi++)
        #pragma unroll
        for (int di = 0; di < 2; di++) {
            int row = r0 + wm * 32 + mi * 16 + di * 8 + g4;
            rmv[mi * 2 + di] = (row < nb) ? row : row - nb;
        }
    float rsum[4] = {0.f, 0.f, 0.f, 0.f};

    for (int ct = z; ct < nct; ct += 2) {
        int c0 = ct << 7;
        float acc[2][8][4];
        #pragma unroll
        for (int mi = 0; mi < 2; mi++)
            #pragma unroll
            for (int ni = 0; ni < 8; ni++)
                #pragma unroll
                for (int j = 0; j < 4; j++) acc[mi][ni][j] = 0.0f;

        __syncthreads();   // stage buffers free of prior-ct readers
        load_stage(sbase, 0, F, r0, c0, 0, tid); CP_COMMIT();
        load_stage(sbase, 1, F, r0, c0, 1, tid); CP_COMMIT();

        for (int kc = 0; kc < 16; kc++) {
            int st = kc % 3;
            CP_WAIT1();            // stage kc arrived
            __syncthreads();       // all warps past stage kc-1 reads; kc visible

            if (kc + 2 < 16) load_stage(sbase, (kc + 2) % 3, F, r0, c0, kc + 2, tid);
            CP_COMMIT();           // always commit to keep group accounting fixed

            uint32_t abase = sbase + (uint32_t)st * STG;
            uint32_t bbase = abase + 16384u;

            uint32_t afr[2][2][4], bfr[2][4][4];
            ldsm_frag(abase, bbase, 0, l, wm, wn, afr[0], bfr[0]);
            #pragma unroll
            for (int s = 0; s < 4; s++) {
                int cu = s & 1;
                if (s < 3)
                    ldsm_frag(abase, bbase, s + 1, l, wm, wn, afr[cu ^ 1], bfr[cu ^ 1]);
                #pragma unroll
                for (int mi = 0; mi < 2; mi++)
                    #pragma unroll
                    for (int ni = 0; ni < 8; ni++)
                        MMA16816(acc[mi][ni], afr[cu][mi],
                                 bfr[cu][ni >> 1][(ni & 1) * 2],
                                 bfr[cu][ni >> 1][(ni & 1) * 2 + 1]);
            }
        }

        // epilogue: exp + neg-pair mask + row accumulate (registers only)
        #pragma unroll
        for (int mi = 0; mi < 2; mi++)
            #pragma unroll
            for (int ni = 0; ni < 8; ni++)
                #pragma unroll
                for (int j = 0; j < 4; j++) {
                    int col = c0 + wn * 64 + ni * 8 + t4 * 2 + (j & 1);
                    int cm = (col < nb) ? col : col - nb;
                    int ri = mi * 2 + (j >> 1);
                    if (col < n2 && cm != rmv[ri])
                        rsum[ri] += exp2f(acc[mi][ni][j] * KEXP);
                }
    }

    // reduce across the 4 lanes of each group (cols), then across the 2 n-warps
    #pragma unroll
    for (int j = 0; j < 4; j++) {
        rsum[j] += __shfl_xor_sync(0xffffffffu, rsum[j], 1);
        rsum[j] += __shfl_xor_sync(0xffffffffu, rsum[j], 2);
    }
    float* red = (float*)smem;  // reuse stage memory (all reads drained)
    __syncthreads();
    if (t4 == 0) {
        #pragma unroll
        for (int mi = 0; mi < 2; mi++)
            #pragma unroll
            for (int di = 0; di < 2; di++) {
                int rl = wm * 32 + mi * 16 + di * 8 + g4;
                red[rl * 2 + wn] = rsum[mi * 2 + di];
            }
    }
    __syncthreads();
    if (tid < 128) {
        int row = r0 + tid;
        if (row < n2)
            g_Ng[z][b * S2 + row] = red[tid * 2 + 0] + red[tid * 2 + 1];
    }
}

// ---------------- kernel D: final loss reduction ----------------
__global__ void kD_final(float* __restrict__ out) {
    __shared__ double sh[8];
    int tid = threadIdx.x;    // 256
    int lane = tid & 31, w = tid >> 5;
    double tot = 0.0;
    for (int b = 0; b < BB; b++) {
        int nb = g_cnt[b];
        int n2 = 2 * nb;
        double local = 0.0;
        for (int idx = tid; idx < n2; idx += 256) {
            int c = (idx < nb) ? idx : idx - nb;
            float pos = g_posexp[b * SS + c];
            float Ng  = g_Ng[0][b * S2 + idx] + g_Ng[1][b * S2 + idx];
            local += (double)log1pf(Ng / pos);
        }
        #pragma unroll
        for (int m = 16; m; m >>= 1) local += __shfl_xor_sync(0xffffffffu, local, m);
        if (lane == 0) sh[w] = local;
        __syncthreads();
        if (w == 0) {
            double x = (lane < 8) ? sh[lane] : 0.0;
            #pragma unroll
            for (int m = 4; m; m >>= 1) x += __shfl_xor_sync(0xffffffffu, x, m);
            if (lane == 0 && n2 > 0) tot += x / (double)n2;
        }
        __syncthreads();
    }
    if (tid == 0) out[0] = (float)(tot / (double)BB);
}

// ---------------- launch ----------------
extern "C" void kernel_launch(void* const* d_in, const int* in_sizes, int n_in,
                              void* d_out, int out_size) {
    const float* h1 = (const float*)d_in[0];
    const float* h2 = (const float*)d_in[1];
    const unsigned char* mask = (const unsigned char*)d_in[2];
    float* out = (float*)d_out;

    static int s_attr_done = 0;
    if (!s_attr_done) {
        cudaFuncSetAttribute(kC_gram, cudaFuncAttributeMaxDynamicSharedMemorySize, SMC_TOTAL);
        s_attr_done = 1;
    }

    kA_scan<<<BB, 256>>>(mask);
    kB_norm<<<BB * SS, 256>>>(h1, h2, mask);
    dim3 gc(S2 / 128, BB, 2);
    kC_gram<<<gc, 256, SMC_TOTAL>>>();
    kD_final<<<1, 256>>>(out);
}

// round 12
// speedup vs baseline: 8.6055x; 1.4215x over previous
#include <cuda_runtime.h>
#include <cuda_bf16.h>
#include <math.h>
#include <stdint.h>

// Problem constants
#define BB 8
#define SS 1536
#define DD 1024
#define S2 3072            // 2*SS
#define NZ 4               // col-split factor for kC (load balance)
// exp(sim/T) = exp2(dot * (1/T)*log2(e)),  T = 0.05
#define KEXP 28.853900817779268f

// ---------------- device scratch ----------------
__device__ __align__(16) __nv_bfloat16 g_fb[(size_t)BB * S2 * DD]; // compact bf16 feats
__device__ float g_posexp[BB * SS];
__device__ int   g_cnt[BB];
__device__ int   g_slot[BB * SS];
__device__ float g_Ng[NZ][BB * S2];
__device__ double g_loss[BB];
__device__ int   g_mstride;   // 1 = uint8 mask, 4 = int32 mask (LSB byte)

// ---------------- PTX helpers (base sm_80+ instructions only) ----------------
__device__ __forceinline__ uint32_t smem_u32(const void* p) {
    uint32_t a;
    asm("{ .reg .u64 t; cvta.to.shared.u64 t, %1; cvt.u32.u64 %0, t; }" : "=r"(a) : "l"(p));
    return a;
}
#define SWZ128(o) ((o) ^ (((o) >> 3) & 0x70))

#define CP16(dst, src) \
    asm volatile("cp.async.cg.shared.global [%0], [%1], 16;" :: "r"(dst), "l"(src) : "memory")
#define CP_COMMIT() asm volatile("cp.async.commit_group;" ::: "memory")
#define CP_WAIT1()  asm volatile("cp.async.wait_group 1;" ::: "memory")

#define LDSM_X4(r, addr) \
    asm volatile("ldmatrix.sync.aligned.m8n8.x4.shared.b16 {%0,%1,%2,%3}, [%4];" \
        : "=r"((r)[0]), "=r"((r)[1]), "=r"((r)[2]), "=r"((r)[3]) : "r"(addr))

#define MMA16816(d, a, b0v, b1v) \
    asm volatile("mma.sync.aligned.m16n8k16.row.col.f32.bf16.bf16.f32 " \
        "{%0,%1,%2,%3}, {%4,%5,%6,%7}, {%8,%9}, {%0,%1,%2,%3};" \
        : "+f"((d)[0]), "+f"((d)[1]), "+f"((d)[2]), "+f"((d)[3]) \
        : "r"((a)[0]), "r"((a)[1]), "r"((a)[2]), "r"((a)[3]), "r"(b0v), "r"(b1v))

// ---------------- generic helpers ----------------
__device__ __forceinline__ float blockReduceF(float v) {
    __shared__ float sh[8];
    int lane = threadIdx.x & 31, w = threadIdx.x >> 5;
    #pragma unroll
    for (int m = 16; m; m >>= 1) v += __shfl_xor_sync(0xffffffffu, v, m);
    if (lane == 0) sh[w] = v;
    __syncthreads();
    if (w == 0) {
        float x = (lane < 8) ? sh[lane] : 0.0f;
        #pragma unroll
        for (int m = 4; m; m >>= 1) x += __shfl_xor_sync(0xffffffffu, x, m);
        if (lane == 0) sh[0] = x;
    }
    __syncthreads();
    float r = sh[0];
    __syncthreads();
    return r;
}

// ---------------- kernel A: detect mask dtype + prefix scan + pad zeroing ----------------
__global__ void kA_scan(const unsigned char* __restrict__ mask) {
    int b = blockIdx.x;
    int tid = threadIdx.x;               // 256 threads
    const int CH = SS / 256;             // 6
    __shared__ int cnts[256];
    __shared__ int s_total;
    __shared__ int s_stride;

    // --- mask dtype detection (every block redundantly; same result) ---
    {
        int c = 0;
        for (int i = tid; i < BB * SS; i += 256) c += mask[i] ? 1 : 0;
        #pragma unroll
        for (int m = 16; m; m >>= 1) c += __shfl_xor_sync(0xffffffffu, c, m);
        if ((tid & 31) == 0) cnts[tid >> 5] = c;
        __syncthreads();
        if (tid == 0) {
            int t = 0;
            #pragma unroll
            for (int i = 0; i < 8; i++) t += cnts[i];
            int st = (t > (BB * SS * 3) / 10) ? 1 : 4;
            s_stride = st;
            g_mstride = st;              // for kB (all blocks write same value)
        }
        __syncthreads();
    }
    int stride = s_stride;
    __syncthreads();

    unsigned char mv[CH];
    int cnt = 0;
    int base = tid * CH;
    #pragma unroll
    for (int j = 0; j < CH; j++) {
        mv[j] = mask[((size_t)b * SS + base + j) * stride];
        cnt += mv[j] ? 1 : 0;
    }
    cnts[tid] = cnt;
    __syncthreads();
    for (int off = 1; off < 256; off <<= 1) {
        int v = (tid >= off) ? cnts[tid - off] : 0;
        __syncthreads();
        cnts[tid] += v;
        __syncthreads();
    }
    int run = cnts[tid] - cnt;
    #pragma unroll
    for (int j = 0; j < CH; j++) {
        if (mv[j]) g_slot[b * SS + base + j] = run++;
    }
    if (tid == 255) { g_cnt[b] = cnts[255]; s_total = cnts[255]; }
    __syncthreads();

    // zero bf16 pad rows [2*nb, round128(2*nb))
    int n2 = 2 * s_total;
    int pad_end = ((n2 + 127) / 128) * 128;
    if (pad_end > S2) pad_end = S2;
    int nz = (pad_end - n2) * DD / 2;   // uint32 count
    uint32_t* dst = (uint32_t*)(g_fb + ((size_t)b * S2 + n2) * DD);
    for (int i = tid; i < nz; i += 256) dst[i] = 0u;
}

// ---------------- kernel B: normalize + compact(bf16) + positive pair(fp32) ----------------
__global__ void kB_norm(const float* __restrict__ h1, const float* __restrict__ h2,
                        const unsigned char* __restrict__ mask) {
    int g = blockIdx.x;
    int b = g / SS, i = g % SS;
    if (!mask[((size_t)b * SS + i) * g_mstride]) return;
    int tid = threadIdx.x;                     // 256 threads, 4 floats each
    int c  = g_slot[b * SS + i];
    int nb = g_cnt[b];

    const float4* p1 = (const float4*)(h1 + ((size_t)b * SS + i) * DD);
    const float4* p2 = (const float4*)(h2 + ((size_t)b * SS + i) * DD);
    float4 v1 = p1[tid];
    float4 v2 = p2[tid];

    float ss1 = blockReduceF(v1.x * v1.x + v1.y * v1.y + v1.z * v1.z + v1.w * v1.w);
    float ss2 = blockReduceF(v2.x * v2.x + v2.y * v2.y + v2.z * v2.z + v2.w * v2.w);
    float inv1 = 1.0f / fmaxf(sqrtf(ss1), 1e-12f);
    float inv2 = 1.0f / fmaxf(sqrtf(ss2), 1e-12f);

    float4 f1 = make_float4(v1.x * inv1, v1.y * inv1, v1.z * inv1, v1.w * inv1);
    float4 f2 = make_float4(v2.x * inv2, v2.y * inv2, v2.z * inv2, v2.w * inv2);

    __nv_bfloat162 a0 = __floats2bfloat162_rn(f1.x, f1.y);
    __nv_bfloat162 a1 = __floats2bfloat162_rn(f1.z, f1.w);
    __nv_bfloat162 b0 = __floats2bfloat162_rn(f2.x, f2.y);
    __nv_bfloat162 b1 = __floats2bfloat162_rn(f2.z, f2.w);
    uint2 pa = make_uint2(*(uint32_t*)&a0, *(uint32_t*)&a1);
    uint2 pb = make_uint2(*(uint32_t*)&b0, *(uint32_t*)&b1);
    ((uint2*)(g_fb + ((size_t)b * S2 + c) * DD))[tid] = pa;
    ((uint2*)(g_fb + ((size_t)b * S2 + nb + c) * DD))[tid] = pb;

    // positive-pair dot in fp32 (full precision)
    float d = blockReduceF(f1.x * f2.x + f1.y * f2.y + f1.z * f2.z + f1.w * f2.w);
    if (tid == 0) g_posexp[b * SS + c] = exp2f(d * KEXP);
}

// ---------------- kernel C: HMMA Gram + fused exp/mask/rowsum ----------------
// 256 threads (8 warps), CTA tile 128x128, warp tile 32x64 (2x8 m16n8k16).
// 3-stage cp.async pipeline (K-chunk 64), ONE __syncthreads per k-chunk,
// register double-buffered ldmatrix fragments.
// grid = (24 rowblocks, B, NZ col splits). Deterministic, no atomics.
#define STG 32768u
#define SMC_TOTAL (3 * 32768)

__device__ __forceinline__ void load_stage(uint32_t sbase, int st, const __nv_bfloat16* F,
                                           int r0, int c0, int kc, int tid) {
    uint32_t aof = (uint32_t)st * STG;
    uint32_t bof = aof + 16384u;
    #pragma unroll
    for (int i = 0; i < 4; i++) {
        int v = tid + i * 256;
        int r = v >> 3, c = v & 7;
        const char* srcA = (const char*)F + (((size_t)(r0 + r)) * DD + kc * 64 + c * 8) * 2;
        CP16(sbase + aof + SWZ128(r * 128 + c * 16), srcA);
        const char* srcB = (const char*)F + (((size_t)(c0 + r)) * DD + kc * 64 + c * 8) * 2;
        CP16(sbase + bof + SWZ128(r * 128 + c * 16), srcB);
    }
}

__device__ __forceinline__ void ldsm_frag(uint32_t abase, uint32_t bbase, int s,
                                          int l, int wm, int wn,
                                          uint32_t afr[2][4], uint32_t bfr[4][4]) {
    #pragma unroll
    for (int mi = 0; mi < 2; mi++) {
        uint32_t off = SWZ128((uint32_t)((wm * 32 + mi * 16 + (l & 15)) * 128
                                         + s * 32 + (l >> 4) * 16));
        LDSM_X4(afr[mi], abase + off);
    }
    #pragma unroll
    for (int p = 0; p < 4; p++) {
        uint32_t off = SWZ128((uint32_t)((wn * 64 + p * 16 + ((l >> 4) & 1) * 8
                                         + (l & 7)) * 128
                                         + s * 32 + ((l >> 3) & 1) * 16));
        LDSM_X4(bfr[p], bbase + off);
    }
}

__global__ void __launch_bounds__(256, 1) kC_gram() {
    extern __shared__ char smem[];
    int b = blockIdx.y;
    int z = blockIdx.z;
    int nb = g_cnt[b];
    int n2 = 2 * nb;
    int r0 = blockIdx.x * 128;
    if (r0 >= n2) return;

    uint32_t sbase = smem_u32(smem);
    const __nv_bfloat16* F = g_fb + (size_t)b * S2 * DD;
    int tid = threadIdx.x;
    int wid = tid >> 5, l = tid & 31;
    int wm = wid & 3, wn = wid >> 2;
    int g4 = l >> 2, t4 = l & 3;
    int nct = (n2 + 127) >> 7;

    // per-thread output rows: mi in {0,1}, di in {0,1}
    int rmv[4];
    #pragma unroll
    for (int mi = 0; mi < 2; mi++)
        #pragma unroll
        for (int di = 0; di < 2; di++) {
            int row = r0 + wm * 32 + mi * 16 + di * 8 + g4;
            rmv[mi * 2 + di] = (row < nb) ? row : row - nb;
        }
    float rsum[4] = {0.f, 0.f, 0.f, 0.f};

    for (int ct = z; ct < nct; ct += NZ) {
        int c0 = ct << 7;
        float acc[2][8][4];
        #pragma unroll
        for (int mi = 0; mi < 2; mi++)
            #pragma unroll
            for (int ni = 0; ni < 8; ni++)
                #pragma unroll
                for (int j = 0; j < 4; j++) acc[mi][ni][j] = 0.0f;

        __syncthreads();   // stage buffers free of prior-ct readers
        load_stage(sbase, 0, F, r0, c0, 0, tid); CP_COMMIT();
        load_stage(sbase, 1, F, r0, c0, 1, tid); CP_COMMIT();

        for (int kc = 0; kc < 16; kc++) {
            int st = kc % 3;
            CP_WAIT1();            // stage kc arrived
            __syncthreads();       // all warps past stage kc-1 reads; kc visible

            if (kc + 2 < 16) load_stage(sbase, (kc + 2) % 3, F, r0, c0, kc + 2, tid);
            CP_COMMIT();           // always commit to keep group accounting fixed

            uint32_t abase = sbase + (uint32_t)st * STG;
            uint32_t bbase = abase + 16384u;

            uint32_t afr[2][2][4], bfr[2][4][4];
            ldsm_frag(abase, bbase, 0, l, wm, wn, afr[0], bfr[0]);
            #pragma unroll
            for (int s = 0; s < 4; s++) {
                int cu = s & 1;
                if (s < 3)
                    ldsm_frag(abase, bbase, s + 1, l, wm, wn, afr[cu ^ 1], bfr[cu ^ 1]);
                #pragma unroll
                for (int mi = 0; mi < 2; mi++)
                    #pragma unroll
                    for (int ni = 0; ni < 8; ni++)
                        MMA16816(acc[mi][ni], afr[cu][mi],
                                 bfr[cu][ni >> 1][(ni & 1) * 2],
                                 bfr[cu][ni >> 1][(ni & 1) * 2 + 1]);
            }
        }

        // epilogue: exp + neg-pair mask + row accumulate (registers only)
        #pragma unroll
        for (int mi = 0; mi < 2; mi++)
            #pragma unroll
            for (int ni = 0; ni < 8; ni++)
                #pragma unroll
                for (int j = 0; j < 4; j++) {
                    int col = c0 + wn * 64 + ni * 8 + t4 * 2 + (j & 1);
                    int cm = (col < nb) ? col : col - nb;
                    int ri = mi * 2 + (j >> 1);
                    if (col < n2 && cm != rmv[ri])
                        rsum[ri] += exp2f(acc[mi][ni][j] * KEXP);
                }
    }

    // reduce across the 4 lanes of each group (cols), then across the 2 n-warps
    #pragma unroll
    for (int j = 0; j < 4; j++) {
        rsum[j] += __shfl_xor_sync(0xffffffffu, rsum[j], 1);
        rsum[j] += __shfl_xor_sync(0xffffffffu, rsum[j], 2);
    }
    float* red = (float*)smem;  // reuse stage memory (all reads drained)
    __syncthreads();
    if (t4 == 0) {
        #pragma unroll
        for (int mi = 0; mi < 2; mi++)
            #pragma unroll
            for (int di = 0; di < 2; di++) {
                int rl = wm * 32 + mi * 16 + di * 8 + g4;
                red[rl * 2 + wn] = rsum[mi * 2 + di];
            }
    }
    __syncthreads();
    if (tid < 128) {
        int row = r0 + tid;
        if (row < n2)
            g_Ng[z][b * S2 + row] = red[tid * 2 + 0] + red[tid * 2 + 1];
    }
}

// ---------------- kernel D: per-batch loss reduction (grid = BB) ----------------
__global__ void kD_batch() {
    __shared__ double sh[8];
    int b = blockIdx.x;
    int tid = threadIdx.x;    // 256
    int lane = tid & 31, w = tid >> 5;
    int nb = g_cnt[b];
    int n2 = 2 * nb;
    double local = 0.0;
    for (int idx = tid; idx < n2; idx += 256) {
        int c = (idx < nb) ? idx : idx - nb;
        float pos = g_posexp[b * SS + c];
        float Ng = 0.0f;
        #pragma unroll
        for (int zz = 0; zz < NZ; zz++) Ng += g_Ng[zz][b * S2 + idx];
        local += (double)log1pf(Ng / pos);
    }
    #pragma unroll
    for (int m = 16; m; m >>= 1) local += __shfl_xor_sync(0xffffffffu, local, m);
    if (lane == 0) sh[w] = local;
    __syncthreads();
    if (w == 0) {
        double x = (lane < 8) ? sh[lane] : 0.0;
        #pragma unroll
        for (int m = 4; m; m >>= 1) x += __shfl_xor_sync(0xffffffffu, x, m);
        if (lane == 0) g_loss[b] = (n2 > 0) ? x / (double)n2 : 0.0;
    }
}

// ---------------- kernel E: combine 8 per-batch losses ----------------
__global__ void kE_combine(float* __restrict__ out) {
    if (threadIdx.x == 0) {
        double t = 0.0;
        #pragma unroll
        for (int b = 0; b < BB; b++) t += g_loss[b];
        out[0] = (float)(t / (double)BB);
    }
}

// ---------------- launch ----------------
extern "C" void kernel_launch(void* const* d_in, const int* in_sizes, int n_in,
                              void* d_out, int out_size) {
    const float* h1 = (const float*)d_in[0];
    const float* h2 = (const float*)d_in[1];
    const unsigned char* mask = (const unsigned char*)d_in[2];
    float* out = (float*)d_out;

    static int s_attr_done = 0;
    if (!s_attr_done) {
        cudaFuncSetAttribute(kC_gram, cudaFuncAttributeMaxDynamicSharedMemorySize, SMC_TOTAL);
        s_attr_done = 1;
    }

    kA_scan<<<BB, 256>>>(mask);
    kB_norm<<<BB * SS, 256>>>(h1, h2, mask);
    dim3 gc(S2 / 128, BB, NZ);
    kC_gram<<<gc, 256, SMC_TOTAL>>>();
    kD_batch<<<BB, 256>>>();
    kE_combine<<<1, 32>>>(out);
}

// round 13
// speedup vs baseline: 11.7563x; 1.3661x over previous
#include <cuda_runtime.h>
#include <cuda_bf16.h>
#include <math.h>
#include <stdint.h>

// Problem constants
#define BB 8
#define SS 1536
#define DD 1024
#define S2 3072            // 2*SS
#define NCTMAX 24          // max 128-col tiles
#define NPAIRS 300         // NCTMAX*(NCTMAX+1)/2
// exp(sim/T) = exp2(dot * (1/T)*log2(e)),  T = 0.05
#define KEXP 28.853900817779268f

// ---------------- device scratch ----------------
__device__ __align__(16) __nv_bfloat16 g_fb[(size_t)BB * S2 * DD]; // compact bf16 feats
__device__ float g_posexp[BB * SS];
__device__ int   g_cnt[BB];
__device__ int   g_slot[BB * SS];
__device__ float g_Ng[NCTMAX][BB * S2];   // partial neg sums, slot-per-tile-index
__device__ double g_loss[BB * 4];
__device__ int   g_mstride;   // 1 = uint8 mask, 4 = int32 mask (LSB byte)

// ---------------- PTX helpers (base sm_80+ instructions only) ----------------
__device__ __forceinline__ uint32_t smem_u32(const void* p) {
    uint32_t a;
    asm("{ .reg .u64 t; cvta.to.shared.u64 t, %1; cvt.u32.u64 %0, t; }" : "=r"(a) : "l"(p));
    return a;
}
#define SWZ128(o) ((o) ^ (((o) >> 3) & 0x70))

#define CP16(dst, src) \
    asm volatile("cp.async.cg.shared.global [%0], [%1], 16;" :: "r"(dst), "l"(src) : "memory")
#define CP_COMMIT() asm volatile("cp.async.commit_group;" ::: "memory")
#define CP_WAIT1()  asm volatile("cp.async.wait_group 1;" ::: "memory")

#define LDSM_X4(r, addr) \
    asm volatile("ldmatrix.sync.aligned.m8n8.x4.shared.b16 {%0,%1,%2,%3}, [%4];" \
        : "=r"((r)[0]), "=r"((r)[1]), "=r"((r)[2]), "=r"((r)[3]) : "r"(addr))

#define MMA16816(d, a, b0v, b1v) \
    asm volatile("mma.sync.aligned.m16n8k16.row.col.f32.bf16.bf16.f32 " \
        "{%0,%1,%2,%3}, {%4,%5,%6,%7}, {%8,%9}, {%0,%1,%2,%3};" \
        : "+f"((d)[0]), "+f"((d)[1]), "+f"((d)[2]), "+f"((d)[3]) \
        : "r"((a)[0]), "r"((a)[1]), "r"((a)[2]), "r"((a)[3]), "r"(b0v), "r"(b1v))

// ---------------- kernel A: detect mask dtype + prefix scan + pad zeroing ----------------
__global__ void kA_scan(const unsigned char* __restrict__ mask) {
    int b = blockIdx.x;
    int tid = threadIdx.x;               // 256 threads
    const int CH = SS / 256;             // 6
    __shared__ int cnts[256];
    __shared__ int s_total;
    __shared__ int s_stride;

    // --- mask dtype detection (every block redundantly; same result) ---
    {
        int c = 0;
        for (int i = tid; i < BB * SS; i += 256) c += mask[i] ? 1 : 0;
        #pragma unroll
        for (int m = 16; m; m >>= 1) c += __shfl_xor_sync(0xffffffffu, c, m);
        if ((tid & 31) == 0) cnts[tid >> 5] = c;
        __syncthreads();
        if (tid == 0) {
            int t = 0;
            #pragma unroll
            for (int i = 0; i < 8; i++) t += cnts[i];
            int st = (t > (BB * SS * 3) / 10) ? 1 : 4;
            s_stride = st;
            g_mstride = st;
        }
        __syncthreads();
    }
    int stride = s_stride;
    __syncthreads();

    unsigned char mv[CH];
    int cnt = 0;
    int base = tid * CH;
    #pragma unroll
    for (int j = 0; j < CH; j++) {
        mv[j] = mask[((size_t)b * SS + base + j) * stride];
        cnt += mv[j] ? 1 : 0;
    }
    cnts[tid] = cnt;
    __syncthreads();
    for (int off = 1; off < 256; off <<= 1) {
        int v = (tid >= off) ? cnts[tid - off] : 0;
        __syncthreads();
        cnts[tid] += v;
        __syncthreads();
    }
    int run = cnts[tid] - cnt;
    #pragma unroll
    for (int j = 0; j < CH; j++) {
        if (mv[j]) g_slot[b * SS + base + j] = run++;
    }
    if (tid == 255) { g_cnt[b] = cnts[255]; s_total = cnts[255]; }
    __syncthreads();

    // zero bf16 pad rows [2*nb, round128(2*nb))
    int n2 = 2 * s_total;
    int pad_end = ((n2 + 127) / 128) * 128;
    if (pad_end > S2) pad_end = S2;
    int nz = (pad_end - n2) * DD / 2;   // uint32 count
    uint32_t* dst = (uint32_t*)(g_fb + ((size_t)b * S2 + n2) * DD);
    for (int i = tid; i < nz; i += 256) dst[i] = 0u;
}

// ---------------- kernel B: normalize + compact(bf16) + positive pair(fp32) ----------------
// single fused 3-value block reduction
__global__ void kB_norm(const float* __restrict__ h1, const float* __restrict__ h2,
                        const unsigned char* __restrict__ mask) {
    int g = blockIdx.x;
    int b = g / SS, i = g % SS;
    if (!mask[((size_t)b * SS + i) * g_mstride]) return;
    int tid = threadIdx.x;                     // 256 threads, 4 floats each
    int c  = g_slot[b * SS + i];
    int nb = g_cnt[b];

    const float4* p1 = (const float4*)(h1 + ((size_t)b * SS + i) * DD);
    const float4* p2 = (const float4*)(h2 + ((size_t)b * SS + i) * DD);
    float4 v1 = p1[tid];
    float4 v2 = p2[tid];

    float sa = v1.x * v1.x + v1.y * v1.y + v1.z * v1.z + v1.w * v1.w;
    float sb = v2.x * v2.x + v2.y * v2.y + v2.z * v2.z + v2.w * v2.w;
    float sc = v1.x * v2.x + v1.y * v2.y + v1.z * v2.z + v1.w * v2.w;

    __shared__ float sh[3][8];
    int lane = tid & 31, w = tid >> 5;
    #pragma unroll
    for (int m = 16; m; m >>= 1) {
        sa += __shfl_xor_sync(0xffffffffu, sa, m);
        sb += __shfl_xor_sync(0xffffffffu, sb, m);
        sc += __shfl_xor_sync(0xffffffffu, sc, m);
    }
    if (lane == 0) { sh[0][w] = sa; sh[1][w] = sb; sh[2][w] = sc; }
    __syncthreads();
    if (w == 0) {
        float xa = (lane < 8) ? sh[0][lane] : 0.0f;
        float xb = (lane < 8) ? sh[1][lane] : 0.0f;
        float xc = (lane < 8) ? sh[2][lane] : 0.0f;
        #pragma unroll
        for (int m = 4; m; m >>= 1) {
            xa += __shfl_xor_sync(0xffffffffu, xa, m);
            xb += __shfl_xor_sync(0xffffffffu, xb, m);
            xc += __shfl_xor_sync(0xffffffffu, xc, m);
        }
        if (lane == 0) { sh[0][0] = xa; sh[1][0] = xb; sh[2][0] = xc; }
    }
    __syncthreads();
    float ss1 = sh[0][0], ss2 = sh[1][0], dot = sh[2][0];

    float inv1 = 1.0f / fmaxf(sqrtf(ss1), 1e-12f);
    float inv2 = 1.0f / fmaxf(sqrtf(ss2), 1e-12f);

    float4 f1 = make_float4(v1.x * inv1, v1.y * inv1, v1.z * inv1, v1.w * inv1);
    float4 f2 = make_float4(v2.x * inv2, v2.y * inv2, v2.z * inv2, v2.w * inv2);

    __nv_bfloat162 a0 = __floats2bfloat162_rn(f1.x, f1.y);
    __nv_bfloat162 a1 = __floats2bfloat162_rn(f1.z, f1.w);
    __nv_bfloat162 b0 = __floats2bfloat162_rn(f2.x, f2.y);
    __nv_bfloat162 b1 = __floats2bfloat162_rn(f2.z, f2.w);
    uint2 pa = make_uint2(*(uint32_t*)&a0, *(uint32_t*)&a1);
    uint2 pb = make_uint2(*(uint32_t*)&b0, *(uint32_t*)&b1);
    ((uint2*)(g_fb + ((size_t)b * S2 + c) * DD))[tid] = pa;
    ((uint2*)(g_fb + ((size_t)b * S2 + nb + c) * DD))[tid] = pb;

    if (tid == 0) g_posexp[b * SS + c] = exp2f(dot * inv1 * inv2 * KEXP);
}

// ---------------- kernel C: symmetric HMMA Gram + fused exp/mask/row+col sums ----
// One 128x128 tile (rb, ct) with ct >= rb per CTA. Off-diagonal tiles scatter
// both row-sums (slot ct -> rows of rb block) and col-sums (slot rb -> rows of
// ct block). 256 threads, warp tile 32x64, 3-stage cp.async pipeline.
#define STG 32768u
#define SMC_TOTAL (3 * 32768)

__device__ __forceinline__ void load_stage(uint32_t sbase, int st, const __nv_bfloat16* F,
                                           int r0, int c0, int kc, int tid) {
    uint32_t aof = (uint32_t)st * STG;
    uint32_t bof = aof + 16384u;
    #pragma unroll
    for (int i = 0; i < 4; i++) {
        int v = tid + i * 256;
        int r = v >> 3, c = v & 7;
        const char* srcA = (const char*)F + (((size_t)(r0 + r)) * DD + kc * 64 + c * 8) * 2;
        CP16(sbase + aof + SWZ128(r * 128 + c * 16), srcA);
        const char* srcB = (const char*)F + (((size_t)(c0 + r)) * DD + kc * 64 + c * 8) * 2;
        CP16(sbase + bof + SWZ128(r * 128 + c * 16), srcB);
    }
}

__device__ __forceinline__ void ldsm_frag(uint32_t abase, uint32_t bbase, int s,
                                          int l, int wm, int wn,
                                          uint32_t afr[2][4], uint32_t bfr[4][4]) {
    #pragma unroll
    for (int mi = 0; mi < 2; mi++) {
        uint32_t off = SWZ128((uint32_t)((wm * 32 + mi * 16 + (l & 15)) * 128
                                         + s * 32 + (l >> 4) * 16));
        LDSM_X4(afr[mi], abase + off);
    }
    #pragma unroll
    for (int p = 0; p < 4; p++) {
        uint32_t off = SWZ128((uint32_t)((wn * 64 + p * 16 + ((l >> 4) & 1) * 8
                                         + (l & 7)) * 128
                                         + s * 32 + ((l >> 3) & 1) * 16));
        LDSM_X4(bfr[p], bbase + off);
    }
}

__global__ void __launch_bounds__(256, 1) kC_gram() {
    extern __shared__ char smem[];
    int b = blockIdx.y;
    int nb = g_cnt[b];
    int n2 = 2 * nb;

    // decode pair index -> (rb, ct), 0 <= rb <= ct < NCTMAX
    int p = blockIdx.x;
    int rb = 0;
    while (p >= NCTMAX - rb) { p -= NCTMAX - rb; rb++; }
    int ct = rb + p;

    int r0 = rb << 7, c0 = ct << 7;
    if (c0 >= n2) return;          // ct >= rb, so this covers r0 too
    bool doCol = (ct > rb);

    uint32_t sbase = smem_u32(smem);
    const __nv_bfloat16* F = g_fb + (size_t)b * S2 * DD;
    int tid = threadIdx.x;
    int wid = tid >> 5, l = tid & 31;
    int wm = wid & 3, wn = wid >> 2;
    int g4 = l >> 2, t4 = l & 3;

    // per-thread output rows (mi, di) and validity
    int rmv[4], rrow[4];
    #pragma unroll
    for (int mi = 0; mi < 2; mi++)
        #pragma unroll
        for (int di = 0; di < 2; di++) {
            int row = r0 + wm * 32 + mi * 16 + di * 8 + g4;
            rrow[mi * 2 + di] = row;
            rmv[mi * 2 + di] = (row < nb) ? row : row - nb;
        }
    float rsum[4] = {0.f, 0.f, 0.f, 0.f};
    float csum[8][2];
    #pragma unroll
    for (int ni = 0; ni < 8; ni++) { csum[ni][0] = 0.f; csum[ni][1] = 0.f; }

    float acc[2][8][4];
    #pragma unroll
    for (int mi = 0; mi < 2; mi++)
        #pragma unroll
        for (int ni = 0; ni < 8; ni++)
            #pragma unroll
            for (int j = 0; j < 4; j++) acc[mi][ni][j] = 0.0f;

    load_stage(sbase, 0, F, r0, c0, 0, tid); CP_COMMIT();
    load_stage(sbase, 1, F, r0, c0, 1, tid); CP_COMMIT();

    for (int kc = 0; kc < 16; kc++) {
        int st = kc % 3;
        CP_WAIT1();            // stage kc arrived
        __syncthreads();       // all warps past stage kc-1 reads; kc visible

        if (kc + 2 < 16) load_stage(sbase, (kc + 2) % 3, F, r0, c0, kc + 2, tid);
        CP_COMMIT();           // keep group accounting fixed

        uint32_t abase = sbase + (uint32_t)st * STG;
        uint32_t bbase = abase + 16384u;

        uint32_t afr[2][2][4], bfr[2][4][4];
        ldsm_frag(abase, bbase, 0, l, wm, wn, afr[0], bfr[0]);
        #pragma unroll
        for (int s = 0; s < 4; s++) {
            int cu = s & 1;
            if (s < 3)
                ldsm_frag(abase, bbase, s + 1, l, wm, wn, afr[cu ^ 1], bfr[cu ^ 1]);
            #pragma unroll
            for (int mi = 0; mi < 2; mi++)
                #pragma unroll
                for (int ni = 0; ni < 8; ni++)
                    MMA16816(acc[mi][ni], afr[cu][mi],
                             bfr[cu][ni >> 1][(ni & 1) * 2],
                             bfr[cu][ni >> 1][(ni & 1) * 2 + 1]);
        }
    }

    // epilogue: exp + neg-pair mask; accumulate row sums and (off-diag) col sums
    #pragma unroll
    for (int mi = 0; mi < 2; mi++)
        #pragma unroll
        for (int ni = 0; ni < 8; ni++)
            #pragma unroll
            for (int j = 0; j < 4; j++) {
                int col = c0 + wn * 64 + ni * 8 + t4 * 2 + (j & 1);
                int cm = (col < nb) ? col : col - nb;
                int ri = mi * 2 + (j >> 1);
                if (col < n2 && cm != rmv[ri]) {
                    float e = exp2f(acc[mi][ni][j] * KEXP);
                    rsum[ri] += e;
                    if (doCol && rrow[ri] < n2) csum[ni][j & 1] += e;
                }
            }

    // row sums: reduce over t4 lanes, stage through smem, combine wn halves
    #pragma unroll
    for (int j = 0; j < 4; j++) {
        rsum[j] += __shfl_xor_sync(0xffffffffu, rsum[j], 1);
        rsum[j] += __shfl_xor_sync(0xffffffffu, rsum[j], 2);
    }
    // col sums: reduce over g4 lanes (stride 4, 8, 16)
    if (doCol) {
        #pragma unroll
        for (int ni = 0; ni < 8; ni++)
            #pragma unroll
            for (int jc = 0; jc < 2; jc++) {
                float v = csum[ni][jc];
                v += __shfl_xor_sync(0xffffffffu, v, 4);
                v += __shfl_xor_sync(0xffffffffu, v, 8);
                v += __shfl_xor_sync(0xffffffffu, v, 16);
                csum[ni][jc] = v;
            }
    }

    float* red  = (float*)smem;          // [128][2] row partials (1 KB)
    float* red2 = (float*)(smem + 1024); // [4][128] col partials (2 KB)
    __syncthreads();   // stage-buffer reads fully drained before reuse
    if (t4 == 0) {
        #pragma unroll
        for (int mi = 0; mi < 2; mi++)
            #pragma unroll
            for (int di = 0; di < 2; di++) {
                int rl = wm * 32 + mi * 16 + di * 8 + g4;
                red[rl * 2 + wn] = rsum[mi * 2 + di];
            }
    }
    if (doCol && l < 4) {   // g4 == 0 lanes hold full g4-sums; t4 = l
        #pragma unroll
        for (int ni = 0; ni < 8; ni++)
            #pragma unroll
            for (int jc = 0; jc < 2; jc++)
                red2[wm * 128 + wn * 64 + ni * 8 + l * 2 + jc] = csum[ni][jc];
    }
    __syncthreads();
    if (tid < 128) {
        int row = r0 + tid;
        if (row < n2)
            g_Ng[ct][b * S2 + row] = red[tid * 2 + 0] + red[tid * 2 + 1];
        if (doCol) {
            int col = c0 + tid;
            if (col < n2)
                g_Ng[rb][b * S2 + col] = red2[tid] + red2[128 + tid]
                                       + red2[256 + tid] + red2[384 + tid];
        }
    }
}

// ---------------- kernel D: per-batch-quarter loss reduction (grid = BB x 4) ----
__global__ void kD_batch() {
    __shared__ double sh[8];
    int b = blockIdx.x;
    int q = blockIdx.y;
    int tid = threadIdx.x;    // 256
    int lane = tid & 31, w = tid >> 5;
    int nb = g_cnt[b];
    int n2 = 2 * nb;
    int nct = (n2 + 127) >> 7;
    double local = 0.0;
    for (int idx = q * 256 + tid; idx < n2; idx += 1024) {
        int c = (idx < nb) ? idx : idx - nb;
        float pos = g_posexp[b * SS + c];
        float Ng = 0.0f;
        for (int s = 0; s < nct; s++) Ng += g_Ng[s][b * S2 + idx];
        local += (double)log1pf(Ng / pos);
    }
    #pragma unroll
    for (int m = 16; m; m >>= 1) local += __shfl_xor_sync(0xffffffffu, local, m);
    if (lane == 0) sh[w] = local;
    __syncthreads();
    if (w == 0) {
        double x = (lane < 8) ? sh[lane] : 0.0;
        #pragma unroll
        for (int m = 4; m; m >>= 1) x += __shfl_xor_sync(0xffffffffu, x, m);
        if (lane == 0) g_loss[b * 4 + q] = (n2 > 0) ? x / (double)n2 : 0.0;
    }
}

// ---------------- kernel E: combine 32 partials ----------------
__global__ void kE_combine(float* __restrict__ out) {
    if (threadIdx.x == 0) {
        double t = 0.0;
        #pragma unroll
        for (int i = 0; i < BB * 4; i++) t += g_loss[i];
        out[0] = (float)(t / (double)BB);
    }
}

// ---------------- launch ----------------
extern "C" void kernel_launch(void* const* d_in, const int* in_sizes, int n_in,
                              void* d_out, int out_size) {
    const float* h1 = (const float*)d_in[0];
    const float* h2 = (const float*)d_in[1];
    const unsigned char* mask = (const unsigned char*)d_in[2];
    float* out = (float*)d_out;

    static int s_attr_done = 0;
    if (!s_attr_done) {
        cudaFuncSetAttribute(kC_gram, cudaFuncAttributeMaxDynamicSharedMemorySize, SMC_TOTAL);
        s_attr_done = 1;
    }

    kA_scan<<<BB, 256>>>(mask);
    kB_norm<<<BB * SS, 256>>>(h1, h2, mask);
    dim3 gc(NPAIRS, BB);
    kC_gram<<<gc, 256, SMC_TOTAL>>>();
    dim3 gd(BB, 4);
    kD_batch<<<gd, 256>>>();
    kE_combine<<<1, 32>>>(out);
}